// round 8
// baseline (speedup 1.0000x reference)
#include <cuda_runtime.h>
#include <math.h>

// ---------------------------------------------------------------------------
// Problem constants
// ---------------------------------------------------------------------------
#define BATCH 4
#define SEQ   2048
#define DMODEL 1024
#define NHEADS 16
#define DK    64
#define DFF   4096
#define MROWS (BATCH * SEQ)   // 8192

// ---------------------------------------------------------------------------
// Scratch (no cudaMalloc allowed)
// ---------------------------------------------------------------------------
__device__ float g_q  [MROWS * DMODEL];
__device__ float g_k  [MROWS * DMODEL];
__device__ float g_v  [MROWS * DMODEL];
__device__ float g_ctx[MROWS * DMODEL];
__device__ float g_t1 [MROWS * DMODEL];
__device__ float g_h  [MROWS * DMODEL];
__device__ float g_hr [MROWS * DMODEL];
__device__ float g_ff [MROWS * DFF];
__device__ float g_xr [MROWS * DMODEL];
__device__ float g_wqr[DMODEL * DMODEL];
__device__ float g_wkr[DMODEL * DMODEL];
__device__ float g_wvr[DMODEL * DMODEL];
__device__ float g_wor[DMODEL * DMODEL];
__device__ float g_w1r[DMODEL * DFF];
__device__ float g_w2r[DFF * DMODEL];

// ---------------------------------------------------------------------------
// Helpers
// ---------------------------------------------------------------------------
__device__ __forceinline__ unsigned cvt_tf32(float x) {
    unsigned r;
    asm("cvt.rna.tf32.f32 %0, %1;" : "=r"(r) : "f"(x));
    return r;
}
__device__ __forceinline__ float rnd_tf32(float x) {
    return __uint_as_float(cvt_tf32(x));
}

__device__ __forceinline__ void mma_tf32(float* c, const unsigned* a, const unsigned* b) {
    asm volatile(
        "mma.sync.aligned.m16n8k8.row.col.f32.tf32.tf32.f32 "
        "{%0,%1,%2,%3}, {%4,%5,%6,%7}, {%8,%9}, {%0,%1,%2,%3};"
        : "+f"(c[0]), "+f"(c[1]), "+f"(c[2]), "+f"(c[3])
        : "r"(a[0]), "r"(a[1]), "r"(a[2]), "r"(a[3]), "r"(b[0]), "r"(b[1]));
}

__device__ __forceinline__ void cp_async16(void* smem_dst, const void* gmem_src) {
    unsigned saddr = (unsigned)__cvta_generic_to_shared(smem_dst);
    asm volatile("cp.async.cg.shared.global [%0], [%1], 16;"
                 :: "r"(saddr), "l"(gmem_src));
}
#define CP_COMMIT() asm volatile("cp.async.commit_group;")
#define CP_WAIT(n)  asm volatile("cp.async.wait_group %0;" :: "n"(n))

// ---------------------------------------------------------------------------
// Elementwise tf32 (rna) rounding: dst[i] = round_tf32(src[i])
// ---------------------------------------------------------------------------
__global__ __launch_bounds__(256) void round_tf32_kernel(
    const float* __restrict__ src, float* __restrict__ dst, int n4)
{
    int i = blockIdx.x * 256 + threadIdx.x;
    if (i < n4) {
        float4 v = ((const float4*)src)[i];
        v.x = rnd_tf32(v.x); v.y = rnd_tf32(v.y);
        v.z = rnd_tf32(v.z); v.w = rnd_tf32(v.w);
        ((float4*)dst)[i] = v;
    }
}

// ---------------------------------------------------------------------------
// TF32 tensor-core GEMM, 2-stage cp.async pipeline.
// C[M,N] = A[M,K] @ B[K,N] + bias[N] (optional ReLU, optional tf32-round out)
// BM=256, BN=128, BK=32. 256 threads = 8 warps (4x2), warp tile 64x64.
// Inputs are assumed pre-rounded to tf32 (raw bits fed to mma).
// ---------------------------------------------------------------------------
#define AS_STRIDE 36
#define BS_STRIDE 132
#define STAGE_FLOATS (256 * AS_STRIDE + 32 * BS_STRIDE)
#define GEMM_SMEM_BYTES (2 * STAGE_FLOATS * 4)

__global__ __launch_bounds__(256, 1) void gemm_tf32(
    int M, int N, int K,
    const float* __restrict__ A, const float* __restrict__ B,
    const float* __restrict__ bias, float* __restrict__ C, int relu, int rnd)
{
    extern __shared__ float sm[];

    const int tid  = threadIdx.x;
    const int lane = tid & 31;
    const int warp = tid >> 5;
    const int wm = (warp >> 1) * 64;   // 0,64,128,192
    const int wn = (warp & 1) * 64;    // 0,64
    const int g = lane >> 2;
    const int t = lane & 3;
    const int cRow = blockIdx.y, cCol = blockIdx.x;

    const int aRow = tid >> 3;         // 0..31
    const int aCol = (tid & 7) * 4;    // 0..28
    const int bRow = tid >> 5;         // 0..7
    const int bCol = (tid & 31) * 4;   // 0..124

    const float* Ag = A + (size_t)(cRow * 256) * K;
    const float* Bg = B + cCol * 128;

    float acc[4][8][4];
    #pragma unroll
    for (int i = 0; i < 4; i++)
        #pragma unroll
        for (int j = 0; j < 8; j++)
            #pragma unroll
            for (int e = 0; e < 4; e++) acc[i][j][e] = 0.f;

    const int NT = K >> 5;

    {
        float* As = sm;
        float* Bs = sm + 256 * AS_STRIDE;
        #pragma unroll
        for (int r = 0; r < 8; r++)
            cp_async16(&As[(aRow + r * 32) * AS_STRIDE + aCol],
                       Ag + (size_t)(aRow + r * 32) * K + aCol);
        #pragma unroll
        for (int r = 0; r < 4; r++)
            cp_async16(&Bs[(bRow + r * 8) * BS_STRIDE + bCol],
                       Bg + (size_t)(bRow + r * 8) * N + bCol);
        CP_COMMIT();
    }

    for (int it = 0; it < NT; it++) {
        if (it + 1 < NT) {
            const int k0 = (it + 1) << 5;
            float* As = sm + ((it + 1) & 1) * STAGE_FLOATS;
            float* Bs = As + 256 * AS_STRIDE;
            #pragma unroll
            for (int r = 0; r < 8; r++)
                cp_async16(&As[(aRow + r * 32) * AS_STRIDE + aCol],
                           Ag + (size_t)(aRow + r * 32) * K + k0 + aCol);
            #pragma unroll
            for (int r = 0; r < 4; r++)
                cp_async16(&Bs[(bRow + r * 8) * BS_STRIDE + bCol],
                           Bg + (size_t)(k0 + bRow + r * 8) * N + bCol);
            CP_COMMIT();
            CP_WAIT(1);
        } else {
            CP_WAIT(0);
        }
        __syncthreads();

        const unsigned* Asu = (const unsigned*)(sm + (it & 1) * STAGE_FLOATS);
        const unsigned* Bsu = Asu + 256 * AS_STRIDE;

        #pragma unroll
        for (int k8 = 0; k8 < 4; k8++) {
            const int kb = k8 * 8;
            unsigned af[4][4], bf[8][2];
            #pragma unroll
            for (int tm = 0; tm < 4; tm++) {
                int r0 = (wm + tm * 16 + g) * AS_STRIDE;
                af[tm][0] = Asu[r0 + kb + t];
                af[tm][1] = Asu[r0 + 8 * AS_STRIDE + kb + t];
                af[tm][2] = Asu[r0 + kb + 4 + t];
                af[tm][3] = Asu[r0 + 8 * AS_STRIDE + kb + 4 + t];
            }
            #pragma unroll
            for (int tn = 0; tn < 8; tn++) {
                bf[tn][0] = Bsu[(kb + t) * BS_STRIDE + wn + tn * 8 + g];
                bf[tn][1] = Bsu[(kb + 4 + t) * BS_STRIDE + wn + tn * 8 + g];
            }
            #pragma unroll
            for (int tm = 0; tm < 4; tm++)
                #pragma unroll
                for (int tn = 0; tn < 8; tn++)
                    mma_tf32(acc[tm][tn], af[tm], bf[tn]);
        }
        __syncthreads();
    }

    #pragma unroll
    for (int tm = 0; tm < 4; tm++) {
        #pragma unroll
        for (int tn = 0; tn < 8; tn++) {
            int row = cRow * 256 + wm + tm * 16 + g;
            int col = cCol * 128 + wn + tn * 8 + 2 * t;
            float2 bb = *(const float2*)(bias + col);
            float2 v0 = make_float2(acc[tm][tn][0] + bb.x, acc[tm][tn][1] + bb.y);
            float2 v1 = make_float2(acc[tm][tn][2] + bb.x, acc[tm][tn][3] + bb.y);
            if (relu) {
                v0.x = fmaxf(v0.x, 0.f); v0.y = fmaxf(v0.y, 0.f);
                v1.x = fmaxf(v1.x, 0.f); v1.y = fmaxf(v1.y, 0.f);
            }
            if (rnd) {
                v0.x = rnd_tf32(v0.x); v0.y = rnd_tf32(v0.y);
                v1.x = rnd_tf32(v1.x); v1.y = rnd_tf32(v1.y);
            }
            *(float2*)(C + (size_t)row * N + col) = v0;
            *(float2*)(C + (size_t)(row + 8) * N + col) = v1;
        }
    }
}

// ---------------------------------------------------------------------------
// Flash attention on tensor cores (tf32 mma.sync m16n8k8).
// Inputs Q/K/V are already exact tf32 (rounded by producing GEMM epilogue),
// so raw-bit feeding == rna semantics. Output ctx is rounded to tf32.
// ---------------------------------------------------------------------------
#define QS_STRIDE 68
#define KS_STRIDE 68
#define VS_STRIDE 72
#define ATTN_SMEM_BYTES (64 * KS_STRIDE * 4 + 64 * VS_STRIDE * 4 + 256)

__global__ __launch_bounds__(256, 2) void attn3(
    const float* __restrict__ Q, const float* __restrict__ K,
    const float* __restrict__ V, const int* __restrict__ mask,
    float* __restrict__ O)
{
    extern __shared__ char smc[];
    float*    Qstage = (float*)smc;
    unsigned* Ks     = (unsigned*)smc;
    unsigned* Vs     = (unsigned*)(smc + 64 * KS_STRIDE * 4);
    float*    maskf  = (float*)(smc + 64 * KS_STRIDE * 4 + 64 * VS_STRIDE * 4);

    const int qt = blockIdx.x, h = blockIdx.y, b = blockIdx.z;
    const int tid  = threadIdx.x;
    const int lane = tid & 31;
    const int warp = tid >> 5;
    const int g = lane >> 2;
    const int t = lane & 3;
    const size_t hoff = (size_t)h * DK;
    const size_t qrow0 = (size_t)b * SEQ + qt * 128;

    #pragma unroll
    for (int it = 0; it < 8; it++) {
        int idx = tid + it * 256;
        int r = idx >> 4;
        int c4 = (idx & 15) << 2;
        float4 v = *(const float4*)(Q + (qrow0 + r) * DMODEL + hoff + c4);
        v.x *= 0.125f; v.y *= 0.125f; v.z *= 0.125f; v.w *= 0.125f;
        *(float4*)&Qstage[r * QS_STRIDE + c4] = v;
    }
    __syncthreads();

    unsigned qf[8][4];
    {
        const int r0 = warp * 16;
        #pragma unroll
        for (int kk = 0; kk < 8; kk++) {
            qf[kk][0] = cvt_tf32(Qstage[(r0 + g)     * QS_STRIDE + kk * 8 + t]);
            qf[kk][1] = cvt_tf32(Qstage[(r0 + 8 + g) * QS_STRIDE + kk * 8 + t]);
            qf[kk][2] = cvt_tf32(Qstage[(r0 + g)     * QS_STRIDE + kk * 8 + 4 + t]);
            qf[kk][3] = cvt_tf32(Qstage[(r0 + 8 + g) * QS_STRIDE + kk * 8 + 4 + t]);
        }
    }
    __syncthreads();

    float m0 = -INFINITY, m1 = -INFINITY, l0 = 0.f, l1 = 0.f;
    float oacc[8][4];
    #pragma unroll
    for (int j = 0; j < 8; j++)
        #pragma unroll
        for (int e = 0; e < 4; e++) oacc[j][e] = 0.f;

    for (int kt = 0; kt < 32; kt++) {
        const size_t kvbase = ((size_t)b * SEQ + kt * 64) * DMODEL + hoff;

        #pragma unroll
        for (int it = 0; it < 4; it++) {
            int idx = tid + it * 256;
            int r = idx >> 4;
            int c4 = (idx & 15) << 2;
            *(uint4*)&Ks[r * KS_STRIDE + c4] =
                *(const uint4*)(K + kvbase + (size_t)r * DMODEL + c4);
            *(uint4*)&Vs[r * VS_STRIDE + c4] =
                *(const uint4*)(V + kvbase + (size_t)r * DMODEL + c4);
        }
        if (tid < 64)
            maskf[tid] = (mask[(size_t)b * SEQ + kt * 64 + tid] == 0) ? -INFINITY : 0.f;
        __syncthreads();

        float sacc[8][4];
        #pragma unroll
        for (int j = 0; j < 8; j++)
            #pragma unroll
            for (int e = 0; e < 4; e++) sacc[j][e] = 0.f;

        #pragma unroll
        for (int kk = 0; kk < 8; kk++) {
            #pragma unroll
            for (int nj = 0; nj < 8; nj++) {
                unsigned bf[2];
                bf[0] = Ks[(nj * 8 + g) * KS_STRIDE + kk * 8 + t];
                bf[1] = Ks[(nj * 8 + g) * KS_STRIDE + kk * 8 + 4 + t];
                mma_tf32(sacc[nj], qf[kk], bf);
            }
        }

        #pragma unroll
        for (int nj = 0; nj < 8; nj++) {
            float mk0 = maskf[nj * 8 + 2 * t];
            float mk1 = maskf[nj * 8 + 2 * t + 1];
            sacc[nj][0] += mk0; sacc[nj][1] += mk1;
            sacc[nj][2] += mk0; sacc[nj][3] += mk1;
        }

        {
            float mx0 = -INFINITY, mx1 = -INFINITY;
            #pragma unroll
            for (int nj = 0; nj < 8; nj++) {
                mx0 = fmaxf(mx0, fmaxf(sacc[nj][0], sacc[nj][1]));
                mx1 = fmaxf(mx1, fmaxf(sacc[nj][2], sacc[nj][3]));
            }
            mx0 = fmaxf(mx0, __shfl_xor_sync(0xffffffffu, mx0, 1));
            mx0 = fmaxf(mx0, __shfl_xor_sync(0xffffffffu, mx0, 2));
            mx1 = fmaxf(mx1, __shfl_xor_sync(0xffffffffu, mx1, 1));
            mx1 = fmaxf(mx1, __shfl_xor_sync(0xffffffffu, mx1, 2));
            float mn0 = fmaxf(m0, mx0), mn1 = fmaxf(m1, mx1);
            float corr0 = __expf(m0 - mn0), corr1 = __expf(m1 - mn1);

            float rs0 = 0.f, rs1 = 0.f;
            #pragma unroll
            for (int nj = 0; nj < 8; nj++) {
                sacc[nj][0] = __expf(sacc[nj][0] - mn0);
                sacc[nj][1] = __expf(sacc[nj][1] - mn0);
                sacc[nj][2] = __expf(sacc[nj][2] - mn1);
                sacc[nj][3] = __expf(sacc[nj][3] - mn1);
                rs0 += sacc[nj][0] + sacc[nj][1];
                rs1 += sacc[nj][2] + sacc[nj][3];
            }
            rs0 += __shfl_xor_sync(0xffffffffu, rs0, 1);
            rs0 += __shfl_xor_sync(0xffffffffu, rs0, 2);
            rs1 += __shfl_xor_sync(0xffffffffu, rs1, 1);
            rs1 += __shfl_xor_sync(0xffffffffu, rs1, 2);
            l0 = l0 * corr0 + rs0;  m0 = mn0;
            l1 = l1 * corr1 + rs1;  m1 = mn1;
            #pragma unroll
            for (int j = 0; j < 8; j++) {
                oacc[j][0] *= corr0; oacc[j][1] *= corr0;
                oacc[j][2] *= corr1; oacc[j][3] *= corr1;
            }
        }

        {
            const int src_lo = (lane & ~3) | (t >> 1);
            const int src_hi = src_lo + 2;
            const bool odd = (t & 1);
            #pragma unroll
            for (int j = 0; j < 8; j++) {
                float c0a = __shfl_sync(0xffffffffu, sacc[j][0], src_lo);
                float c1a = __shfl_sync(0xffffffffu, sacc[j][1], src_lo);
                float c0b = __shfl_sync(0xffffffffu, sacc[j][0], src_hi);
                float c1b = __shfl_sync(0xffffffffu, sacc[j][1], src_hi);
                float c2a = __shfl_sync(0xffffffffu, sacc[j][2], src_lo);
                float c3a = __shfl_sync(0xffffffffu, sacc[j][3], src_lo);
                float c2b = __shfl_sync(0xffffffffu, sacc[j][2], src_hi);
                float c3b = __shfl_sync(0xffffffffu, sacc[j][3], src_hi);
                unsigned af[4];
                af[0] = __float_as_uint(odd ? c1a : c0a);
                af[1] = __float_as_uint(odd ? c3a : c2a);
                af[2] = __float_as_uint(odd ? c1b : c0b);
                af[3] = __float_as_uint(odd ? c3b : c2b);
                #pragma unroll
                for (int jj = 0; jj < 8; jj++) {
                    unsigned bf[2];
                    bf[0] = Vs[(j * 8 + t)     * VS_STRIDE + jj * 8 + g];
                    bf[1] = Vs[(j * 8 + t + 4) * VS_STRIDE + jj * 8 + g];
                    mma_tf32(oacc[jj], af, bf);
                }
            }
        }
        __syncthreads();
    }

    {
        const float inv0 = 1.f / l0, inv1 = 1.f / l1;
        const size_t r0 = qrow0 + warp * 16 + g;
        #pragma unroll
        for (int jj = 0; jj < 8; jj++) {
            int col = jj * 8 + 2 * t;
            *(float2*)(O + r0 * DMODEL + hoff + col) =
                make_float2(rnd_tf32(oacc[jj][0] * inv0), rnd_tf32(oacc[jj][1] * inv0));
            *(float2*)(O + (r0 + 8) * DMODEL + hoff + col) =
                make_float2(rnd_tf32(oacc[jj][2] * inv1), rnd_tf32(oacc[jj][3] * inv1));
        }
    }
}

// ---------------------------------------------------------------------------
// out[row] = LayerNorm(a[row] + b[row]) * gamma + beta.
// Optionally also writes a tf32-rounded copy (out_r) for downstream GEMMs.
// ---------------------------------------------------------------------------
__global__ __launch_bounds__(256) void add_ln_kernel(
    const float* __restrict__ a, const float* __restrict__ bsrc,
    const float* __restrict__ g, const float* __restrict__ be,
    float* __restrict__ out, float* __restrict__ out_r)
{
    const int row = blockIdx.x;
    const int tid = threadIdx.x;
    const float* pa = a + (size_t)row * DMODEL;
    const float* pb = bsrc + (size_t)row * DMODEL;

    float v[4];
    float sum = 0.f, sq = 0.f;
    #pragma unroll
    for (int i = 0; i < 4; i++) {
        int c = tid + i * 256;
        float x = pa[c] + pb[c];
        v[i] = x;
        sum += x;
        sq += x * x;
    }
    #pragma unroll
    for (int o = 16; o > 0; o >>= 1) {
        sum += __shfl_xor_sync(0xffffffffu, sum, o);
        sq  += __shfl_xor_sync(0xffffffffu, sq,  o);
    }
    __shared__ float ssum[8], ssq[8];
    if ((tid & 31) == 0) { ssum[tid >> 5] = sum; ssq[tid >> 5] = sq; }
    __syncthreads();
    if (tid < 32) {
        float s2 = (tid < 8) ? ssum[tid] : 0.f;
        float q2 = (tid < 8) ? ssq[tid] : 0.f;
        #pragma unroll
        for (int o = 4; o > 0; o >>= 1) {
            s2 += __shfl_xor_sync(0xffffffffu, s2, o);
            q2 += __shfl_xor_sync(0xffffffffu, q2, o);
        }
        if (tid == 0) { ssum[0] = s2; ssq[0] = q2; }
    }
    __syncthreads();
    const float mu   = ssum[0] * (1.f / DMODEL);
    const float var  = ssq[0] * (1.f / DMODEL) - mu * mu;
    const float rstd = rsqrtf(var + 1e-5f);

    float* po = out + (size_t)row * DMODEL;
    float* pr = out_r ? out_r + (size_t)row * DMODEL : nullptr;
    #pragma unroll
    for (int i = 0; i < 4; i++) {
        int c = tid + i * 256;
        float y = (v[i] - mu) * rstd * g[c] + be[c];
        po[c] = y;
        if (pr) pr[c] = rnd_tf32(y);
    }
}

// ---------------------------------------------------------------------------
// Launch
// ---------------------------------------------------------------------------
extern "C" void kernel_launch(void* const* d_in, const int* in_sizes, int n_in,
                              void* d_out, int out_size)
{
    (void)in_sizes; (void)n_in; (void)out_size;
    const float* x    = (const float*)d_in[0];
    const int*   mask = (const int*)  d_in[1];
    const float* w_q  = (const float*)d_in[2];
    const float* b_q  = (const float*)d_in[3];
    const float* w_k  = (const float*)d_in[4];
    const float* b_k  = (const float*)d_in[5];
    const float* w_v  = (const float*)d_in[6];
    const float* b_v  = (const float*)d_in[7];
    const float* w_o  = (const float*)d_in[8];
    const float* b_o  = (const float*)d_in[9];
    const float* w1   = (const float*)d_in[10];
    const float* b1   = (const float*)d_in[11];
    const float* w2   = (const float*)d_in[12];
    const float* b2   = (const float*)d_in[13];
    const float* g1   = (const float*)d_in[14];
    const float* be1  = (const float*)d_in[15];
    const float* g2   = (const float*)d_in[16];
    const float* be2  = (const float*)d_in[17];

    float *q, *k, *v, *ctx, *t1, *h, *hr, *ff;
    float *xr, *wqr, *wkr, *wvr, *wor, *w1r, *w2r;
    cudaGetSymbolAddress((void**)&q,   g_q);
    cudaGetSymbolAddress((void**)&k,   g_k);
    cudaGetSymbolAddress((void**)&v,   g_v);
    cudaGetSymbolAddress((void**)&ctx, g_ctx);
    cudaGetSymbolAddress((void**)&t1,  g_t1);
    cudaGetSymbolAddress((void**)&h,   g_h);
    cudaGetSymbolAddress((void**)&hr,  g_hr);
    cudaGetSymbolAddress((void**)&ff,  g_ff);
    cudaGetSymbolAddress((void**)&xr,  g_xr);
    cudaGetSymbolAddress((void**)&wqr, g_wqr);
    cudaGetSymbolAddress((void**)&wkr, g_wkr);
    cudaGetSymbolAddress((void**)&wvr, g_wvr);
    cudaGetSymbolAddress((void**)&wor, g_wor);
    cudaGetSymbolAddress((void**)&w1r, g_w1r);
    cudaGetSymbolAddress((void**)&w2r, g_w2r);

    cudaFuncSetAttribute(gemm_tf32, cudaFuncAttributeMaxDynamicSharedMemorySize,
                         GEMM_SMEM_BYTES);
    cudaFuncSetAttribute(attn3, cudaFuncAttributeMaxDynamicSharedMemorySize,
                         ATTN_SMEM_BYTES);

    // ---- pre-round GEMM inputs to tf32 (rna) ----
    {
        const int TB = 256;
        int n;
        n = MROWS * DMODEL / 4;  round_tf32_kernel<<<(n + TB - 1) / TB, TB>>>(x,   xr,  n);
        n = DMODEL * DMODEL / 4; round_tf32_kernel<<<(n + TB - 1) / TB, TB>>>(w_q, wqr, n);
        n = DMODEL * DMODEL / 4; round_tf32_kernel<<<(n + TB - 1) / TB, TB>>>(w_k, wkr, n);
        n = DMODEL * DMODEL / 4; round_tf32_kernel<<<(n + TB - 1) / TB, TB>>>(w_v, wvr, n);
        n = DMODEL * DMODEL / 4; round_tf32_kernel<<<(n + TB - 1) / TB, TB>>>(w_o, wor, n);
        n = DMODEL * DFF / 4;    round_tf32_kernel<<<(n + TB - 1) / TB, TB>>>(w1,  w1r, n);
        n = DFF * DMODEL / 4;    round_tf32_kernel<<<(n + TB - 1) / TB, TB>>>(w2,  w2r, n);
    }

    dim3 blk(256);
    dim3 gProj(DMODEL / 128, MROWS / 256);   // (8, 32)
    dim3 gFF1(DFF / 128, MROWS / 256);       // (32, 32)
    dim3 gAtt(SEQ / 128, NHEADS, BATCH);     // (16, 16, 4)

    // QKV projections: outputs rounded to tf32 (consumed by attn mma)
    gemm_tf32<<<gProj, blk, GEMM_SMEM_BYTES>>>(MROWS, DMODEL, DMODEL, xr, wqr, b_q, q, 0, 1);
    gemm_tf32<<<gProj, blk, GEMM_SMEM_BYTES>>>(MROWS, DMODEL, DMODEL, xr, wkr, b_k, k, 0, 1);
    gemm_tf32<<<gProj, blk, GEMM_SMEM_BYTES>>>(MROWS, DMODEL, DMODEL, xr, wvr, b_v, v, 0, 1);

    attn3<<<gAtt, blk, ATTN_SMEM_BYTES>>>(q, k, v, mask, ctx);  // ctx rounded

    gemm_tf32<<<gProj, blk, GEMM_SMEM_BYTES>>>(MROWS, DMODEL, DMODEL, ctx, wor, b_o, t1, 0, 0);
    add_ln_kernel<<<MROWS, 256>>>(x, t1, g1, be1, h, hr);

    gemm_tf32<<<gFF1, blk, GEMM_SMEM_BYTES>>>(MROWS, DFF, DMODEL, hr, w1r, b1, ff, 1, 1);
    gemm_tf32<<<gProj, blk, GEMM_SMEM_BYTES>>>(MROWS, DMODEL, DFF, ff, w2r, b2, t1, 0, 0);
    add_ln_kernel<<<MROWS, 256>>>(h, t1, g2, be2, (float*)d_out, nullptr);
}